// round 1
// baseline (speedup 1.0000x reference)
#include <cuda_runtime.h>

#define BB 8
#define SS 2048
#define DD 1024
#define MTOT (BB*SS)   // 16384

// Scratch (device globals; allocation APIs are forbidden)
__device__ float g_q  [(size_t)MTOT * DD];
__device__ float g_k  [(size_t)MTOT * DD];
__device__ float g_v  [(size_t)MTOT * DD];
__device__ float g_sc [(size_t)BB * SS * SS];   // 134 MB
__device__ float g_att[(size_t)MTOT * DD];
__device__ float g_h  [(size_t)MTOT * DD];
__device__ float g_x  [(size_t)MTOT * DD];

enum { EPI_NONE = 0, EPI_BIAS = 1, EPI_RES = 2, EPI_RELU = 4 };

// C[M,N] = A[M,K] @ op(B)  (+bias +residual +relu per EPI)
// TB=false: B is [K,N] row-major. TB=true: B is [N,K] row-major (compute A@B^T).
// Block tile 128x128, K-step 8, 256 threads, 8x8 per thread (split quadrants).
// Requires: M%128==0, N%128==0, K%8==0 (all true for this problem).
template<int EPI, bool TB>
__global__ void __launch_bounds__(256)
sgemm128(const float* __restrict__ A,
         const float* __restrict__ Bm,
         float* __restrict__ C,
         const float* __restrict__ bias,
         const float* __restrict__ resid,
         int M, int N, int K,
         long sA, long sB, long sC)
{
    __shared__ float As[8][128];
    __shared__ float Bs[8][128];

    const int tid = threadIdx.x;
    const int tx = tid & 15;   // 0..15 -> col quad
    const int ty = tid >> 4;   // 0..15 -> row quad

    const float* Ag = A  + (long)blockIdx.z * sA;
    const float* Bg = Bm + (long)blockIdx.z * sB;
    float*       Cg = C  + (long)blockIdx.z * sC;

    const int m0 = blockIdx.y * 128;
    const int n0 = blockIdx.x * 128;

    // loader indexing (transposed scatter path): 128 rows x 8 k
    const int lrow = tid >> 1;          // 0..127
    const int lkq  = (tid & 1) * 4;     // 0 or 4
    // NN B loader: 8 k-rows x 128 cols
    const int brow = tid >> 5;          // 0..7
    const int bcol = (tid & 31) * 4;    // 0..124

    float acc[8][8];
#pragma unroll
    for (int i = 0; i < 8; i++)
#pragma unroll
        for (int j = 0; j < 8; j++) acc[i][j] = 0.f;

    for (int k0 = 0; k0 < K; k0 += 8) {
        float4 av = *reinterpret_cast<const float4*>(Ag + (long)(m0 + lrow) * K + k0 + lkq);
        As[lkq + 0][lrow] = av.x;
        As[lkq + 1][lrow] = av.y;
        As[lkq + 2][lrow] = av.z;
        As[lkq + 3][lrow] = av.w;
        if (TB) {
            float4 bv = *reinterpret_cast<const float4*>(Bg + (long)(n0 + lrow) * K + k0 + lkq);
            Bs[lkq + 0][lrow] = bv.x;
            Bs[lkq + 1][lrow] = bv.y;
            Bs[lkq + 2][lrow] = bv.z;
            Bs[lkq + 3][lrow] = bv.w;
        } else {
            float4 bv = *reinterpret_cast<const float4*>(Bg + (long)(k0 + brow) * N + n0 + bcol);
            *reinterpret_cast<float4*>(&Bs[brow][bcol]) = bv;
        }
        __syncthreads();

#pragma unroll
        for (int kk = 0; kk < 8; kk++) {
            float4 a0 = *reinterpret_cast<const float4*>(&As[kk][ty * 4]);
            float4 a1 = *reinterpret_cast<const float4*>(&As[kk][64 + ty * 4]);
            float4 b0 = *reinterpret_cast<const float4*>(&Bs[kk][tx * 4]);
            float4 b1 = *reinterpret_cast<const float4*>(&Bs[kk][64 + tx * 4]);
            float a[8] = {a0.x, a0.y, a0.z, a0.w, a1.x, a1.y, a1.z, a1.w};
            float b[8] = {b0.x, b0.y, b0.z, b0.w, b1.x, b1.y, b1.z, b1.w};
#pragma unroll
            for (int i = 0; i < 8; i++)
#pragma unroll
                for (int j = 0; j < 8; j++)
                    acc[i][j] = fmaf(a[i], b[j], acc[i][j]);
        }
        __syncthreads();
    }

    // epilogue + store
#pragma unroll
    for (int i = 0; i < 8; i++) {
        const int r = m0 + ((i < 4) ? (ty * 4 + i) : (64 + ty * 4 + i - 4));
#pragma unroll
        for (int jh = 0; jh < 2; jh++) {
            const int c = n0 + (jh ? (64 + tx * 4) : (tx * 4));
            float o[4];
#pragma unroll
            for (int j = 0; j < 4; j++) o[j] = acc[i][jh * 4 + j];
            if (EPI & EPI_BIAS) {
                const float4 bv = *reinterpret_cast<const float4*>(bias + c);
                o[0] += bv.x; o[1] += bv.y; o[2] += bv.z; o[3] += bv.w;
            }
            if (EPI & EPI_RES) {
                const float4 rv = *reinterpret_cast<const float4*>(resid + (long)r * N + c);
                o[0] += rv.x; o[1] += rv.y; o[2] += rv.z; o[3] += rv.w;
            }
            if (EPI & EPI_RELU) {
#pragma unroll
                for (int j = 0; j < 4; j++) o[j] = fmaxf(o[j], 0.f);
            }
            float4 ov = make_float4(o[0], o[1], o[2], o[3]);
            *reinterpret_cast<float4*>(Cg + (long)r * N + c) = ov;
        }
    }
}

// In-place row softmax over rows of length SS=2048. One block (256 thr) per row.
__global__ void __launch_bounds__(256) softmax2048(float* __restrict__ sc)
{
    __shared__ float red[8];
    __shared__ float bcast;
    const int t = threadIdx.x;
    float* row = sc + (size_t)blockIdx.x * SS;

    float v[8];
#pragma unroll
    for (int i = 0; i < 8; i++) v[i] = row[t + i * 256];

    float m = v[0];
#pragma unroll
    for (int i = 1; i < 8; i++) m = fmaxf(m, v[i]);
#pragma unroll
    for (int o = 16; o; o >>= 1) m = fmaxf(m, __shfl_xor_sync(0xffffffffu, m, o));
    if ((t & 31) == 0) red[t >> 5] = m;
    __syncthreads();
    if (t == 0) {
        float mm = red[0];
#pragma unroll
        for (int i = 1; i < 8; i++) mm = fmaxf(mm, red[i]);
        bcast = mm;
    }
    __syncthreads();
    m = bcast;

    float s = 0.f;
#pragma unroll
    for (int i = 0; i < 8; i++) { v[i] = expf(v[i] - m); s += v[i]; }
#pragma unroll
    for (int o = 16; o; o >>= 1) s += __shfl_xor_sync(0xffffffffu, s, o);
    __syncthreads();            // protect red[] reuse
    if ((t & 31) == 0) red[t >> 5] = s;
    __syncthreads();
    if (t == 0) {
        float ss = 0.f;
#pragma unroll
        for (int i = 0; i < 8; i++) ss += red[i];
        bcast = 1.f / ss;
    }
    __syncthreads();
    const float inv = bcast;
#pragma unroll
    for (int i = 0; i < 8; i++) row[t + i * 256] = v[i] * inv;
}

// out[r] = sum_d x[r][d] * W2[d] + b2[0]; warp per row, 8 rows per block.
__global__ void __launch_bounds__(256)
out_dot(const float* __restrict__ x, const float* __restrict__ W2,
        const float* __restrict__ b2, float* __restrict__ out)
{
    const int warp = threadIdx.x >> 5;
    const int lane = threadIdx.x & 31;
    const long row = (long)blockIdx.x * 8 + warp;
    const float* xr = x + row * DD;
    float s = 0.f;
#pragma unroll
    for (int i = 0; i < DD / 32; i++)
        s += xr[i * 32 + lane] * W2[i * 32 + lane];
#pragma unroll
    for (int o = 16; o; o >>= 1) s += __shfl_xor_sync(0xffffffffu, s, o);
    if (lane == 0) out[row] = s + b2[0];
}

extern "C" void kernel_launch(void* const* d_in, const int* in_sizes, int n_in,
                              void* d_out, int out_size)
{
    const float* visual = (const float*)d_in[0];
    const float* audio  = (const float*)d_in[1];
    const float* Wq = (const float*)d_in[2];
    const float* bq = (const float*)d_in[3];
    const float* Wk = (const float*)d_in[4];
    const float* bk = (const float*)d_in[5];
    const float* Wv = (const float*)d_in[6];
    const float* bv = (const float*)d_in[7];
    const float* Wo = (const float*)d_in[8];
    const float* bo = (const float*)d_in[9];
    const float* W1 = (const float*)d_in[10];
    const float* b1 = (const float*)d_in[11];
    const float* W2 = (const float*)d_in[12];
    const float* b2 = (const float*)d_in[13];
    float* out = (float*)d_out;

    float *q, *k, *v, *sc, *att, *h, *x;
    cudaGetSymbolAddress((void**)&q,   g_q);
    cudaGetSymbolAddress((void**)&k,   g_k);
    cudaGetSymbolAddress((void**)&v,   g_v);
    cudaGetSymbolAddress((void**)&sc,  g_sc);
    cudaGetSymbolAddress((void**)&att, g_att);
    cudaGetSymbolAddress((void**)&h,   g_h);
    cudaGetSymbolAddress((void**)&x,   g_x);

    const dim3 blk(256);
    const dim3 gp(DD / 128, MTOT / 128, 1);     // projection-shaped GEMMs
    const dim3 gs(SS / 128, SS / 128, BB);      // scores
    const dim3 ga(DD / 128, SS / 128, BB);      // attn @ V

    // Q = visual @ Wq + bq ; K = audio @ Wk + bk ; V = audio @ Wv + bv
    sgemm128<EPI_BIAS, false><<<gp, blk>>>(visual, Wq, q, bq, nullptr,
                                           MTOT, DD, DD, 0, 0, 0);
    sgemm128<EPI_BIAS, false><<<gp, blk>>>(audio, Wk, k, bk, nullptr,
                                           MTOT, DD, DD, 0, 0, 0);
    sgemm128<EPI_BIAS, false><<<gp, blk>>>(audio, Wv, v, bv, nullptr,
                                           MTOT, DD, DD, 0, 0, 0);

    // scores[b] = Q[b] @ K[b]^T  (NT, batched over z)
    sgemm128<EPI_NONE, true><<<gs, blk>>>(q, k, sc, nullptr, nullptr,
                                          SS, SS, DD,
                                          (long)SS * DD, (long)SS * DD, (long)SS * SS);

    // softmax rows (in place)
    softmax2048<<<MTOT, 256>>>(sc);

    // att[b] = softmax(scores[b]) @ V[b]
    sgemm128<EPI_NONE, false><<<ga, blk>>>(sc, v, att, nullptr, nullptr,
                                           SS, DD, SS,
                                           (long)SS * SS, (long)SS * DD, (long)SS * DD);

    // h = att @ Wo + bo + visual
    sgemm128<EPI_BIAS | EPI_RES, false><<<gp, blk>>>(att, Wo, h, bo, visual,
                                                     MTOT, DD, DD, 0, 0, 0);

    // x = relu(h @ W1 + b1)
    sgemm128<EPI_BIAS | EPI_RELU, false><<<gp, blk>>>(h, W1, x, b1, nullptr,
                                                      MTOT, DD, DD, 0, 0, 0);

    // out = x @ W2 + b2
    out_dot<<<MTOT / 8, 256>>>(x, W2, b2, out);
}

// round 3
// speedup vs baseline: 1.2266x; 1.2266x over previous
#include <cuda_runtime.h>

#define BB 8
#define SS 2048
#define DD 1024
#define MTOT (BB*SS)   // 16384

// Scratch (device globals; allocation APIs are forbidden)
__device__ float g_q  [(size_t)MTOT * DD];
__device__ float g_k  [(size_t)MTOT * DD];
__device__ float g_v  [(size_t)MTOT * DD];
__device__ float g_sc [(size_t)BB * SS * SS];   // 134 MB
__device__ float g_att[(size_t)MTOT * DD];
__device__ float g_h  [(size_t)MTOT * DD];
__device__ float g_x  [(size_t)MTOT * DD];

enum { EPI_NONE = 0, EPI_BIAS = 1, EPI_RES = 2, EPI_RELU = 4 };

// ---- packed f32x2 helpers (sm_100+), carried in b64 regs ----
typedef unsigned long long u64;
__device__ __forceinline__ void fma2(u64& d, u64 a, u64 b) {
    asm("fma.rn.f32x2 %0, %1, %2, %0;" : "+l"(d) : "l"(a), "l"(b));
}
__device__ __forceinline__ u64 dup2(float x) {
    u64 r;
    asm("mov.b64 %0, {%1, %1};" : "=l"(r) : "f"(x));
    return r;
}
__device__ __forceinline__ float2 unpk(u64 d) {
    float2 f;
    asm("mov.b64 {%0, %1}, %2;" : "=f"(f.x), "=f"(f.y) : "l"(d));
    return f;
}

// C[M,N] = A[M,K] @ op(B)  (+bias +residual +relu per EPI)
// TB=false: B is [K,N] row-major. TB=true: B is [N,K] row-major (A@B^T).
// Block 128x128, K-step 8, 256 threads, 8x8 per thread.
// A tile stored pair-interleaved: As[kk][2r]=A(row r), As[kk][2r+1]=A(row r+64),
// so one LDS.128 yields two f32x2 operand pairs (a_r, a_{r+64}) with no packing.
// Accumulators are f32x2: acc[ip][j] = (C[row 4ty+ip][col j], C[row 64+4ty+ip][col j]).
// Double-buffered smem, one __syncthreads per k-step, register prefetch.
template<int EPI, bool TB>
__global__ void __launch_bounds__(256)
sgemm128(const float* __restrict__ A,
         const float* __restrict__ Bm,
         float* __restrict__ C,
         const float* __restrict__ bias,
         const float* __restrict__ resid,
         int M, int N, int K,
         long sA, long sB, long sC)
{
    __shared__ float As[2][8][128];
    __shared__ float Bs[2][8][128];

    const int tid = threadIdx.x;
    const int tx = tid & 15;   // 0..15 -> col group
    const int ty = tid >> 4;   // 0..15 -> row group

    const float* Ag = A  + (long)blockIdx.z * sA;
    const float* Bg = Bm + (long)blockIdx.z * sB;
    float*       Cg = C  + (long)blockIdx.z * sC;

    const int m0 = blockIdx.y * 128;
    const int n0 = blockIdx.x * 128;

    // loader indexing: 128 rows x 8 k (two float4 halves per row-pair of threads)
    const int lrow = tid >> 1;          // 0..127
    const int lkq  = (tid & 1) * 4;     // 0 or 4
    const int ai   = (lrow < 64) ? (2 * lrow) : (2 * (lrow - 64) + 1);  // interleave
    // NN B loader: 8 k-rows x 128 cols
    const int brow = tid >> 5;          // 0..7
    const int bcol = (tid & 31) * 4;    // 0..124

    const float* Aptr  = Ag + (long)(m0 + lrow) * K + lkq;           // + k0
    const float* BptrT = Bg + (long)(n0 + lrow) * K + lkq;           // + k0   (TB)
    const float* BptrN = Bg + (long)brow * N + n0 + bcol;            // + k0*N (NN)

    u64 acc[4][8];
#pragma unroll
    for (int i = 0; i < 4; i++)
#pragma unroll
        for (int j = 0; j < 8; j++) acc[i][j] = 0ull;

    // prologue: load k0=0 tile
    float4 av = *reinterpret_cast<const float4*>(Aptr);
    float4 bv = TB ? *reinterpret_cast<const float4*>(BptrT)
                   : *reinterpret_cast<const float4*>(BptrN);
    {
        As[0][lkq + 0][ai] = av.x;
        As[0][lkq + 1][ai] = av.y;
        As[0][lkq + 2][ai] = av.z;
        As[0][lkq + 3][ai] = av.w;
        if (TB) {
            Bs[0][lkq + 0][lrow] = bv.x;
            Bs[0][lkq + 1][lrow] = bv.y;
            Bs[0][lkq + 2][lrow] = bv.z;
            Bs[0][lkq + 3][lrow] = bv.w;
        } else {
            *reinterpret_cast<float4*>(&Bs[0][brow][bcol]) = bv;
        }
    }
    __syncthreads();

    int buf = 0;
    for (int k0 = 0; k0 < K; k0 += 8) {
        const bool more = (k0 + 8 < K);
        if (more) {
            av = *reinterpret_cast<const float4*>(Aptr + k0 + 8);
            bv = TB ? *reinterpret_cast<const float4*>(BptrT + k0 + 8)
                    : *reinterpret_cast<const float4*>(BptrN + (long)(k0 + 8) * N);
        }

#pragma unroll
        for (int kk = 0; kk < 8; kk++) {
            // A pairs: (row 4ty+i, row 64+4ty+i), i=0..3, via 2 LDS.128
            ulonglong2 aq0 = *reinterpret_cast<const ulonglong2*>(&As[buf][kk][8 * ty]);
            ulonglong2 aq1 = *reinterpret_cast<const ulonglong2*>(&As[buf][kk][8 * ty + 4]);
            const u64 ap[4] = {aq0.x, aq0.y, aq1.x, aq1.y};
            // B values, duplicated into f32x2 lanes
            float4 b0 = *reinterpret_cast<const float4*>(&Bs[buf][kk][tx * 4]);
            float4 b1 = *reinterpret_cast<const float4*>(&Bs[buf][kk][64 + tx * 4]);
            const u64 bd[8] = {dup2(b0.x), dup2(b0.y), dup2(b0.z), dup2(b0.w),
                               dup2(b1.x), dup2(b1.y), dup2(b1.z), dup2(b1.w)};
#pragma unroll
            for (int ip = 0; ip < 4; ip++)
#pragma unroll
                for (int j = 0; j < 8; j++)
                    fma2(acc[ip][j], ap[ip], bd[j]);
        }

        if (more) {
            const int nb = buf ^ 1;
            As[nb][lkq + 0][ai] = av.x;
            As[nb][lkq + 1][ai] = av.y;
            As[nb][lkq + 2][ai] = av.z;
            As[nb][lkq + 3][ai] = av.w;
            if (TB) {
                Bs[nb][lkq + 0][lrow] = bv.x;
                Bs[nb][lkq + 1][lrow] = bv.y;
                Bs[nb][lkq + 2][lrow] = bv.z;
                Bs[nb][lkq + 3][lrow] = bv.w;
            } else {
                *reinterpret_cast<float4*>(&Bs[nb][brow][bcol]) = bv;
            }
        }
        buf ^= 1;
        __syncthreads();
    }

    // epilogue: acc[ip][j] = (lo: row m0+4ty+ip, hi: row m0+64+4ty+ip), col per j
#pragma unroll
    for (int ip = 0; ip < 4; ip++) {
        const int rlo = m0 + 4 * ty + ip;
        const int rhi = rlo + 64;
#pragma unroll
        for (int jh = 0; jh < 2; jh++) {
            const int c = n0 + (jh ? (64 + tx * 4) : (tx * 4));
            float lo[4], hi[4];
#pragma unroll
            for (int j = 0; j < 4; j++) {
                float2 f = unpk(acc[ip][jh * 4 + j]);
                lo[j] = f.x; hi[j] = f.y;
            }
            if (EPI & EPI_BIAS) {
                const float4 bb = *reinterpret_cast<const float4*>(bias + c);
                lo[0] += bb.x; lo[1] += bb.y; lo[2] += bb.z; lo[3] += bb.w;
                hi[0] += bb.x; hi[1] += bb.y; hi[2] += bb.z; hi[3] += bb.w;
            }
            if (EPI & EPI_RES) {
                const float4 r0 = *reinterpret_cast<const float4*>(resid + (long)rlo * N + c);
                const float4 r1 = *reinterpret_cast<const float4*>(resid + (long)rhi * N + c);
                lo[0] += r0.x; lo[1] += r0.y; lo[2] += r0.z; lo[3] += r0.w;
                hi[0] += r1.x; hi[1] += r1.y; hi[2] += r1.z; hi[3] += r1.w;
            }
            if (EPI & EPI_RELU) {
#pragma unroll
                for (int j = 0; j < 4; j++) {
                    lo[j] = fmaxf(lo[j], 0.f);
                    hi[j] = fmaxf(hi[j], 0.f);
                }
            }
            *reinterpret_cast<float4*>(Cg + (long)rlo * N + c) = make_float4(lo[0], lo[1], lo[2], lo[3]);
            *reinterpret_cast<float4*>(Cg + (long)rhi * N + c) = make_float4(hi[0], hi[1], hi[2], hi[3]);
        }
    }
}

// In-place row softmax over rows of length SS=2048. One block (256 thr) per row.
__global__ void __launch_bounds__(256) softmax2048(float* __restrict__ sc)
{
    __shared__ float red[8];
    __shared__ float bcast;
    const int t = threadIdx.x;
    float* row = sc + (size_t)blockIdx.x * SS;

    float v[8];
#pragma unroll
    for (int i = 0; i < 8; i++) v[i] = row[t + i * 256];

    float m = v[0];
#pragma unroll
    for (int i = 1; i < 8; i++) m = fmaxf(m, v[i]);
#pragma unroll
    for (int o = 16; o; o >>= 1) m = fmaxf(m, __shfl_xor_sync(0xffffffffu, m, o));
    if ((t & 31) == 0) red[t >> 5] = m;
    __syncthreads();
    if (t == 0) {
        float mm = red[0];
#pragma unroll
        for (int i = 1; i < 8; i++) mm = fmaxf(mm, red[i]);
        bcast = mm;
    }
    __syncthreads();
    m = bcast;

    float s = 0.f;
#pragma unroll
    for (int i = 0; i < 8; i++) { v[i] = expf(v[i] - m); s += v[i]; }
#pragma unroll
    for (int o = 16; o; o >>= 1) s += __shfl_xor_sync(0xffffffffu, s, o);
    __syncthreads();
    if ((t & 31) == 0) red[t >> 5] = s;
    __syncthreads();
    if (t == 0) {
        float ss = 0.f;
#pragma unroll
        for (int i = 0; i < 8; i++) ss += red[i];
        bcast = 1.f / ss;
    }
    __syncthreads();
    const float inv = bcast;
#pragma unroll
    for (int i = 0; i < 8; i++) row[t + i * 256] = v[i] * inv;
}

// out[r] = sum_d x[r][d] * W2[d] + b2[0]; warp per row, 8 rows per block.
__global__ void __launch_bounds__(256)
out_dot(const float* __restrict__ x, const float* __restrict__ W2,
        const float* __restrict__ b2, float* __restrict__ out)
{
    const int warp = threadIdx.x >> 5;
    const int lane = threadIdx.x & 31;
    const long row = (long)blockIdx.x * 8 + warp;
    const float* xr = x + row * DD;
    float s = 0.f;
#pragma unroll
    for (int i = 0; i < DD / 32; i++)
        s += xr[i * 32 + lane] * W2[i * 32 + lane];
#pragma unroll
    for (int o = 16; o; o >>= 1) s += __shfl_xor_sync(0xffffffffu, s, o);
    if (lane == 0) out[row] = s + b2[0];
}

extern "C" void kernel_launch(void* const* d_in, const int* in_sizes, int n_in,
                              void* d_out, int out_size)
{
    const float* visual = (const float*)d_in[0];
    const float* audio  = (const float*)d_in[1];
    const float* Wq = (const float*)d_in[2];
    const float* bq = (const float*)d_in[3];
    const float* Wk = (const float*)d_in[4];
    const float* bk = (const float*)d_in[5];
    const float* Wv = (const float*)d_in[6];
    const float* bv = (const float*)d_in[7];
    const float* Wo = (const float*)d_in[8];
    const float* bo = (const float*)d_in[9];
    const float* W1 = (const float*)d_in[10];
    const float* b1 = (const float*)d_in[11];
    const float* W2 = (const float*)d_in[12];
    const float* b2 = (const float*)d_in[13];
    float* out = (float*)d_out;

    float *q, *k, *v, *sc, *att, *h, *x;
    cudaGetSymbolAddress((void**)&q,   g_q);
    cudaGetSymbolAddress((void**)&k,   g_k);
    cudaGetSymbolAddress((void**)&v,   g_v);
    cudaGetSymbolAddress((void**)&sc,  g_sc);
    cudaGetSymbolAddress((void**)&att, g_att);
    cudaGetSymbolAddress((void**)&h,   g_h);
    cudaGetSymbolAddress((void**)&x,   g_x);

    const dim3 blk(256);
    const dim3 gp(DD / 128, MTOT / 128, 1);     // projection-shaped GEMMs
    const dim3 gs(SS / 128, SS / 128, BB);      // scores
    const dim3 ga(DD / 128, SS / 128, BB);      // attn @ V

    // Q = visual @ Wq + bq ; K = audio @ Wk + bk ; V = audio @ Wv + bv
    sgemm128<EPI_BIAS, false><<<gp, blk>>>(visual, Wq, q, bq, nullptr,
                                           MTOT, DD, DD, 0, 0, 0);
    sgemm128<EPI_BIAS, false><<<gp, blk>>>(audio, Wk, k, bk, nullptr,
                                           MTOT, DD, DD, 0, 0, 0);
    sgemm128<EPI_BIAS, false><<<gp, blk>>>(audio, Wv, v, bv, nullptr,
                                           MTOT, DD, DD, 0, 0, 0);

    // scores[b] = Q[b] @ K[b]^T  (NT, batched over z)
    sgemm128<EPI_NONE, true><<<gs, blk>>>(q, k, sc, nullptr, nullptr,
                                          SS, SS, DD,
                                          (long)SS * DD, (long)SS * DD, (long)SS * SS);

    // softmax rows (in place)
    softmax2048<<<MTOT, 256>>>(sc);

    // att[b] = softmax(scores[b]) @ V[b]
    sgemm128<EPI_NONE, false><<<ga, blk>>>(sc, v, att, nullptr, nullptr,
                                           SS, DD, SS,
                                           (long)SS * SS, (long)SS * DD, (long)SS * DD);

    // h = att @ Wo + bo + visual
    sgemm128<EPI_BIAS | EPI_RES, false><<<gp, blk>>>(att, Wo, h, bo, visual,
                                                     MTOT, DD, DD, 0, 0, 0);

    // x = relu(h @ W1 + b1)
    sgemm128<EPI_BIAS | EPI_RELU, false><<<gp, blk>>>(h, W1, x, b1, nullptr,
                                                      MTOT, DD, DD, 0, 0, 0);

    // out = x @ W2 + b2
    out_dot<<<MTOT / 8, 256>>>(x, W2, b2, out);
}

// round 4
// speedup vs baseline: 1.2274x; 1.0006x over previous
#include <cuda_runtime.h>

#define BB 8
#define SS 2048
#define DD 1024
#define MTOT (BB*SS)   // 16384

// Scratch (device globals; allocation APIs are forbidden)
__device__ float g_q  [(size_t)MTOT * DD];
__device__ float g_k  [(size_t)MTOT * DD];
__device__ float g_v  [(size_t)MTOT * DD];
__device__ float g_sc [(size_t)BB * SS * SS];   // 134 MB
__device__ float g_att[(size_t)MTOT * DD];
__device__ float g_h  [(size_t)MTOT * DD];
__device__ float g_x  [(size_t)MTOT * DD];

enum { EPI_NONE = 0, EPI_BIAS = 1, EPI_RES = 2, EPI_RELU = 4 };

// ---- packed f32x2 helpers (sm_100+), carried in b64 regs ----
typedef unsigned long long u64;
__device__ __forceinline__ void fma2(u64& d, u64 a, u64 b) {
    asm("fma.rn.f32x2 %0, %1, %2, %0;" : "+l"(d) : "l"(a), "l"(b));
}
__device__ __forceinline__ u64 dup2(float x) {
    u64 r;
    asm("mov.b64 %0, {%1, %1};" : "=l"(r) : "f"(x));
    return r;
}
__device__ __forceinline__ float2 unpk(u64 d) {
    float2 f;
    asm("mov.b64 {%0, %1}, %2;" : "=f"(f.x), "=f"(f.y) : "l"(d));
    return f;
}

// C[M,N] = A[M,K] @ op(B)  (+bias +residual +relu per EPI)
// TB=false: B is [K,N] row-major. TB=true: B is [N,K] row-major (A@B^T).
// Block 128x128, K-step 8, 256 threads, 8x8 per thread.
// A tile stored pair-interleaved: As[kk][2r]=A(row r), As[kk][2r+1]=A(row r+64),
// so one LDS.128 yields two f32x2 operand pairs (a_r, a_{r+64}) with no packing.
// Accumulators are f32x2: acc[ip][j] = (C[row 4ty+ip][col j], C[row 64+4ty+ip][col j]).
// Double-buffered smem, one __syncthreads per k-step, register prefetch.
template<int EPI, bool TB>
__global__ void __launch_bounds__(256)
sgemm128(const float* __restrict__ A,
         const float* __restrict__ Bm,
         float* __restrict__ C,
         const float* __restrict__ bias,
         const float* __restrict__ resid,
         int M, int N, int K,
         long sA, long sB, long sC)
{
    __shared__ float As[2][8][128];
    __shared__ float Bs[2][8][128];

    const int tid = threadIdx.x;
    const int tx = tid & 15;   // 0..15 -> col group
    const int ty = tid >> 4;   // 0..15 -> row group

    const float* Ag = A  + (long)blockIdx.z * sA;
    const float* Bg = Bm + (long)blockIdx.z * sB;
    float*       Cg = C  + (long)blockIdx.z * sC;

    const int m0 = blockIdx.y * 128;
    const int n0 = blockIdx.x * 128;

    // loader indexing: 128 rows x 8 k (two float4 halves per row-pair of threads)
    const int lrow = tid >> 1;          // 0..127
    const int lkq  = (tid & 1) * 4;     // 0 or 4
    const int ai   = (lrow < 64) ? (2 * lrow) : (2 * (lrow - 64) + 1);  // interleave
    // NN B loader: 8 k-rows x 128 cols
    const int brow = tid >> 5;          // 0..7
    const int bcol = (tid & 31) * 4;    // 0..124

    const float* Aptr  = Ag + (long)(m0 + lrow) * K + lkq;           // + k0
    const float* BptrT = Bg + (long)(n0 + lrow) * K + lkq;           // + k0   (TB)
    const float* BptrN = Bg + (long)brow * N + n0 + bcol;            // + k0*N (NN)

    u64 acc[4][8];
#pragma unroll
    for (int i = 0; i < 4; i++)
#pragma unroll
        for (int j = 0; j < 8; j++) acc[i][j] = 0ull;

    // prologue: load k0=0 tile
    float4 av = *reinterpret_cast<const float4*>(Aptr);
    float4 bv = TB ? *reinterpret_cast<const float4*>(BptrT)
                   : *reinterpret_cast<const float4*>(BptrN);
    {
        As[0][lkq + 0][ai] = av.x;
        As[0][lkq + 1][ai] = av.y;
        As[0][lkq + 2][ai] = av.z;
        As[0][lkq + 3][ai] = av.w;
        if (TB) {
            Bs[0][lkq + 0][lrow] = bv.x;
            Bs[0][lkq + 1][lrow] = bv.y;
            Bs[0][lkq + 2][lrow] = bv.z;
            Bs[0][lkq + 3][lrow] = bv.w;
        } else {
            *reinterpret_cast<float4*>(&Bs[0][brow][bcol]) = bv;
        }
    }
    __syncthreads();

    int buf = 0;
    for (int k0 = 0; k0 < K; k0 += 8) {
        const bool more = (k0 + 8 < K);
        if (more) {
            av = *reinterpret_cast<const float4*>(Aptr + k0 + 8);
            bv = TB ? *reinterpret_cast<const float4*>(BptrT + k0 + 8)
                    : *reinterpret_cast<const float4*>(BptrN + (long)(k0 + 8) * N);
        }

#pragma unroll
        for (int kk = 0; kk < 8; kk++) {
            // A pairs: (row 4ty+i, row 64+4ty+i), i=0..3, via 2 LDS.128
            ulonglong2 aq0 = *reinterpret_cast<const ulonglong2*>(&As[buf][kk][8 * ty]);
            ulonglong2 aq1 = *reinterpret_cast<const ulonglong2*>(&As[buf][kk][8 * ty + 4]);
            const u64 ap[4] = {aq0.x, aq0.y, aq1.x, aq1.y};
            // B values, duplicated into f32x2 lanes
            float4 b0 = *reinterpret_cast<const float4*>(&Bs[buf][kk][tx * 4]);
            float4 b1 = *reinterpret_cast<const float4*>(&Bs[buf][kk][64 + tx * 4]);
            const u64 bd[8] = {dup2(b0.x), dup2(b0.y), dup2(b0.z), dup2(b0.w),
                               dup2(b1.x), dup2(b1.y), dup2(b1.z), dup2(b1.w)};
#pragma unroll
            for (int ip = 0; ip < 4; ip++)
#pragma unroll
                for (int j = 0; j < 8; j++)
                    fma2(acc[ip][j], ap[ip], bd[j]);
        }

        if (more) {
            const int nb = buf ^ 1;
            As[nb][lkq + 0][ai] = av.x;
            As[nb][lkq + 1][ai] = av.y;
            As[nb][lkq + 2][ai] = av.z;
            As[nb][lkq + 3][ai] = av.w;
            if (TB) {
                Bs[nb][lkq + 0][lrow] = bv.x;
                Bs[nb][lkq + 1][lrow] = bv.y;
                Bs[nb][lkq + 2][lrow] = bv.z;
                Bs[nb][lkq + 3][lrow] = bv.w;
            } else {
                *reinterpret_cast<float4*>(&Bs[nb][brow][bcol]) = bv;
            }
        }
        buf ^= 1;
        __syncthreads();
    }

    // epilogue: acc[ip][j] = (lo: row m0+4ty+ip, hi: row m0+64+4ty+ip), col per j
#pragma unroll
    for (int ip = 0; ip < 4; ip++) {
        const int rlo = m0 + 4 * ty + ip;
        const int rhi = rlo + 64;
#pragma unroll
        for (int jh = 0; jh < 2; jh++) {
            const int c = n0 + (jh ? (64 + tx * 4) : (tx * 4));
            float lo[4], hi[4];
#pragma unroll
            for (int j = 0; j < 4; j++) {
                float2 f = unpk(acc[ip][jh * 4 + j]);
                lo[j] = f.x; hi[j] = f.y;
            }
            if (EPI & EPI_BIAS) {
                const float4 bb = *reinterpret_cast<const float4*>(bias + c);
                lo[0] += bb.x; lo[1] += bb.y; lo[2] += bb.z; lo[3] += bb.w;
                hi[0] += bb.x; hi[1] += bb.y; hi[2] += bb.z; hi[3] += bb.w;
            }
            if (EPI & EPI_RES) {
                const float4 r0 = *reinterpret_cast<const float4*>(resid + (long)rlo * N + c);
                const float4 r1 = *reinterpret_cast<const float4*>(resid + (long)rhi * N + c);
                lo[0] += r0.x; lo[1] += r0.y; lo[2] += r0.z; lo[3] += r0.w;
                hi[0] += r1.x; hi[1] += r1.y; hi[2] += r1.z; hi[3] += r1.w;
            }
            if (EPI & EPI_RELU) {
#pragma unroll
                for (int j = 0; j < 4; j++) {
                    lo[j] = fmaxf(lo[j], 0.f);
                    hi[j] = fmaxf(hi[j], 0.f);
                }
            }
            *reinterpret_cast<float4*>(Cg + (long)rlo * N + c) = make_float4(lo[0], lo[1], lo[2], lo[3]);
            *reinterpret_cast<float4*>(Cg + (long)rhi * N + c) = make_float4(hi[0], hi[1], hi[2], hi[3]);
        }
    }
}

// In-place row softmax over rows of length SS=2048. One block (256 thr) per row.
__global__ void __launch_bounds__(256) softmax2048(float* __restrict__ sc)
{
    __shared__ float red[8];
    __shared__ float bcast;
    const int t = threadIdx.x;
    float* row = sc + (size_t)blockIdx.x * SS;

    float v[8];
#pragma unroll
    for (int i = 0; i < 8; i++) v[i] = row[t + i * 256];

    float m = v[0];
#pragma unroll
    for (int i = 1; i < 8; i++) m = fmaxf(m, v[i]);
#pragma unroll
    for (int o = 16; o; o >>= 1) m = fmaxf(m, __shfl_xor_sync(0xffffffffu, m, o));
    if ((t & 31) == 0) red[t >> 5] = m;
    __syncthreads();
    if (t == 0) {
        float mm = red[0];
#pragma unroll
        for (int i = 1; i < 8; i++) mm = fmaxf(mm, red[i]);
        bcast = mm;
    }
    __syncthreads();
    m = bcast;

    float s = 0.f;
#pragma unroll
    for (int i = 0; i < 8; i++) { v[i] = expf(v[i] - m); s += v[i]; }
#pragma unroll
    for (int o = 16; o; o >>= 1) s += __shfl_xor_sync(0xffffffffu, s, o);
    __syncthreads();
    if ((t & 31) == 0) red[t >> 5] = s;
    __syncthreads();
    if (t == 0) {
        float ss = 0.f;
#pragma unroll
        for (int i = 0; i < 8; i++) ss += red[i];
        bcast = 1.f / ss;
    }
    __syncthreads();
    const float inv = bcast;
#pragma unroll
    for (int i = 0; i < 8; i++) row[t + i * 256] = v[i] * inv;
}

// out[r] = sum_d x[r][d] * W2[d] + b2[0]; warp per row, 8 rows per block.
__global__ void __launch_bounds__(256)
out_dot(const float* __restrict__ x, const float* __restrict__ W2,
        const float* __restrict__ b2, float* __restrict__ out)
{
    const int warp = threadIdx.x >> 5;
    const int lane = threadIdx.x & 31;
    const long row = (long)blockIdx.x * 8 + warp;
    const float* xr = x + row * DD;
    float s = 0.f;
#pragma unroll
    for (int i = 0; i < DD / 32; i++)
        s += xr[i * 32 + lane] * W2[i * 32 + lane];
#pragma unroll
    for (int o = 16; o; o >>= 1) s += __shfl_xor_sync(0xffffffffu, s, o);
    if (lane == 0) out[row] = s + b2[0];
}

extern "C" void kernel_launch(void* const* d_in, const int* in_sizes, int n_in,
                              void* d_out, int out_size)
{
    const float* visual = (const float*)d_in[0];
    const float* audio  = (const float*)d_in[1];
    const float* Wq = (const float*)d_in[2];
    const float* bq = (const float*)d_in[3];
    const float* Wk = (const float*)d_in[4];
    const float* bk = (const float*)d_in[5];
    const float* Wv = (const float*)d_in[6];
    const float* bv = (const float*)d_in[7];
    const float* Wo = (const float*)d_in[8];
    const float* bo = (const float*)d_in[9];
    const float* W1 = (const float*)d_in[10];
    const float* b1 = (const float*)d_in[11];
    const float* W2 = (const float*)d_in[12];
    const float* b2 = (const float*)d_in[13];
    float* out = (float*)d_out;

    float *q, *k, *v, *sc, *att, *h, *x;
    cudaGetSymbolAddress((void**)&q,   g_q);
    cudaGetSymbolAddress((void**)&k,   g_k);
    cudaGetSymbolAddress((void**)&v,   g_v);
    cudaGetSymbolAddress((void**)&sc,  g_sc);
    cudaGetSymbolAddress((void**)&att, g_att);
    cudaGetSymbolAddress((void**)&h,   g_h);
    cudaGetSymbolAddress((void**)&x,   g_x);

    const dim3 blk(256);
    const dim3 gp(DD / 128, MTOT / 128, 1);     // projection-shaped GEMMs
    const dim3 gs(SS / 128, SS / 128, BB);      // scores
    const dim3 ga(DD / 128, SS / 128, BB);      // attn @ V

    // Q = visual @ Wq + bq ; K = audio @ Wk + bk ; V = audio @ Wv + bv
    sgemm128<EPI_BIAS, false><<<gp, blk>>>(visual, Wq, q, bq, nullptr,
                                           MTOT, DD, DD, 0, 0, 0);
    sgemm128<EPI_BIAS, false><<<gp, blk>>>(audio, Wk, k, bk, nullptr,
                                           MTOT, DD, DD, 0, 0, 0);
    sgemm128<EPI_BIAS, false><<<gp, blk>>>(audio, Wv, v, bv, nullptr,
                                           MTOT, DD, DD, 0, 0, 0);

    // scores[b] = Q[b] @ K[b]^T  (NT, batched over z)
    sgemm128<EPI_NONE, true><<<gs, blk>>>(q, k, sc, nullptr, nullptr,
                                          SS, SS, DD,
                                          (long)SS * DD, (long)SS * DD, (long)SS * SS);

    // softmax rows (in place)
    softmax2048<<<MTOT, 256>>>(sc);

    // att[b] = softmax(scores[b]) @ V[b]
    sgemm128<EPI_NONE, false><<<ga, blk>>>(sc, v, att, nullptr, nullptr,
                                           SS, DD, SS,
                                           (long)SS * SS, (long)SS * DD, (long)SS * DD);

    // h = att @ Wo + bo + visual
    sgemm128<EPI_BIAS | EPI_RES, false><<<gp, blk>>>(att, Wo, h, bo, visual,
                                                     MTOT, DD, DD, 0, 0, 0);

    // x = relu(h @ W1 + b1)
    sgemm128<EPI_BIAS | EPI_RELU, false><<<gp, blk>>>(h, W1, x, b1, nullptr,
                                                      MTOT, DD, DD, 0, 0, 0);

    // out = x @ W2 + b2
    out_dot<<<MTOT / 8, 256>>>(x, W2, b2, out);
}

// round 6
// speedup vs baseline: 2.1763x; 1.7731x over previous
#include <cuda_runtime.h>
#include <cuda_bf16.h>
#include <cstdint>

typedef __nv_bfloat16 bf16;
typedef unsigned int u32;
typedef unsigned long long u64;

#define BB 8
#define SS 2048
#define DD 1024
#define MTOT (BB*SS)

// ---------------- scratch pool ----------------
constexpr size_t SZ_ACT = (size_t)MTOT * DD * 2;
constexpr size_t SZ_P   = (size_t)BB * SS * SS * 2;
constexpr size_t SZ_W   = (size_t)DD * DD * 2;
constexpr size_t SZ_SC  = (size_t)BB * SS * SS * 4;
constexpr size_t SZ_X   = (size_t)MTOT * DD * 4;
constexpr int N_ACT = 18;
constexpr size_t O_P0 = (size_t)N_ACT * SZ_ACT;
constexpr size_t O_P1 = O_P0 + SZ_P;
constexpr size_t O_WT = O_P1 + SZ_P;
constexpr size_t O_SC = O_WT + 12 * SZ_W;
constexpr size_t O_X  = O_SC + SZ_SC;
__device__ __align__(256) char g_pool[O_X + SZ_X];

// ---------------- helpers ----------------
__device__ __forceinline__ u32 smem_to_u32(const void* p) {
    u32 a;
    asm("{ .reg .u64 t; cvta.to.shared.u64 t, %1; cvt.u32.u64 %0, t; }" : "=r"(a) : "l"(p));
    return a;
}
#define SWZ(off) ((off) ^ (((off) >> 3) & 0x70))

__device__ __forceinline__ void cp16(u32 s, const void* g) {
    asm volatile("cp.async.cg.shared.global [%0], [%1], 16;" :: "r"(s), "l"(g));
}
__device__ __forceinline__ void ldsm4(u32& r0, u32& r1, u32& r2, u32& r3, u32 a) {
    asm volatile("ldmatrix.sync.aligned.m8n8.x4.shared.b16 {%0,%1,%2,%3}, [%4];"
                 : "=r"(r0), "=r"(r1), "=r"(r2), "=r"(r3) : "r"(a));
}
__device__ __forceinline__ void mma16816(float* c, const u32* a, const u32* b) {
    asm("mma.sync.aligned.m16n8k16.row.col.f32.bf16.bf16.f32 "
        "{%0,%1,%2,%3},{%4,%5,%6,%7},{%8,%9},{%0,%1,%2,%3};"
        : "+f"(c[0]), "+f"(c[1]), "+f"(c[2]), "+f"(c[3])
        : "r"(a[0]), "r"(a[1]), "r"(a[2]), "r"(a[3]), "r"(b[0]), "r"(b[1]));
}

__device__ __forceinline__ void split2f(float v, bf16& a, bf16& b) {
    a = __float2bfloat16(v);
    b = __float2bfloat16(v - __bfloat162float(a));
}
__device__ __forceinline__ void split3f(float v, bf16& a, bf16& b, bf16& c) {
    a = __float2bfloat16(v);
    float r = v - __bfloat162float(a);
    b = __float2bfloat16(r);
    c = __float2bfloat16(r - __bfloat162float(b));
}
__device__ __forceinline__ void st_bf2(bf16* p, bf16 a, bf16 b) {
    __nv_bfloat162 t; t.x = a; t.y = b;
    *reinterpret_cast<__nv_bfloat162*>(p) = t;
}

enum { EPI_BIAS = 1, EPI_RES = 2, EPI_RELU = 4, EPI_BIASR = 8 };

struct GArgs {
    const bf16 *A0, *A1, *A2, *B0, *B1, *B2;
    float* C;
    bf16 *S0, *S1, *S2;
    const float *bias, *biasR, *resid;
    int K, lda, ldb, ldc;
    long sA, sB, sC;
};

// C[M,N] = sum_pp A_{PI[pp]}[M,K] @ B_{PJ[pp]}[N,K]^T  (bf16 splits, fp32 accum)
// Block 128x128, K-chunks of 64 bf16 (SW128 rows), cp.async double buffer,
// 8 warps 2(M)x4(N), warp tile 64x32, mma.sync m16n8k16.
template<int NSA, int NSB, int NP, int EPI, int NEMIT>
__global__ void __launch_bounds__(256, 1) mma_gemm(const GArgs ga)
{
    extern __shared__ char dynsmem[];
    constexpr int NT = NSA + NSB;
    constexpr int TILE = 16384;
    constexpr int PI[6] = {0, 0, 1, 1, 2, 0};
    constexpr int PJ[6] = {0, 1, 0, 1, 0, 2};

    const int tid = threadIdx.x, wid = tid >> 5, lane = tid & 31;
    const u32 tiles = (smem_to_u32(dynsmem) + 1023u) & ~1023u;
    const long z = blockIdx.z;
    const int m0 = blockIdx.y * 128, n0 = blockIdx.x * 128;

    const bf16* src[NT];
    if (NSA > 0) src[0] = ga.A0 + z * ga.sA + (long)m0 * ga.lda;
    if (NSA > 1) src[1] = ga.A1 + z * ga.sA + (long)m0 * ga.lda;
    if (NSA > 2) src[2] = ga.A2 + z * ga.sA + (long)m0 * ga.lda;
    if (NSB > 0) src[NSA + 0] = ga.B0 + z * ga.sB + (long)n0 * ga.ldb;
    if (NSB > 1) src[NSA + 1] = ga.B1 + z * ga.sB + (long)n0 * ga.ldb;
    if (NSB > 2) src[NSA + 2] = ga.B2 + z * ga.sB + (long)n0 * ga.ldb;

    const int wy = wid & 1, wx = wid >> 1;       // warp tile: rows wy*64, cols wx*32

    float acc[4][4][4];
#pragma unroll
    for (int i = 0; i < 4; i++)
#pragma unroll
        for (int j = 0; j < 4; j++)
#pragma unroll
            for (int r = 0; r < 4; r++) acc[i][j][r] = 0.f;

    // ldmatrix lane-address components (byte offsets within a tile)
    const int aRow = wy * 64 + (lane & 15);            // + mf*16
    const int aKb  = (lane >> 4) * 16;                 // + kk*32
    const int bRow = wx * 32 + (lane & 7) + ((lane >> 4) & 1) * 8;  // + nfp*16
    const int bKb  = ((lane >> 3) & 1) * 16;

    auto load_chunk = [&](int k0, int buf) {
        const u32 sb = tiles + (u32)buf * (NT * TILE);
#pragma unroll
        for (int t = 0; t < NT; t++) {
            const int ld = (t < NSA) ? ga.lda : ga.ldb;
#pragma unroll
            for (int u = 0; u < 4; u++) {
                const int i = u * 256 + tid;
                const int r = i >> 3, c16 = i & 7;
                cp16(sb + t * TILE + SWZ((r << 7) + (c16 << 4)),
                     src[t] + (long)r * ld + k0 + c16 * 8);
            }
        }
        asm volatile("cp.async.commit_group;" ::: "memory");
    };

    const int NC = ga.K >> 6;
    load_chunk(0, 0);
    for (int c = 0; c < NC; ++c) {
        if (c + 1 < NC) {
            load_chunk((c + 1) << 6, (c + 1) & 1);
            asm volatile("cp.async.wait_group 1;" ::: "memory");
        } else {
            asm volatile("cp.async.wait_group 0;" ::: "memory");
        }
        __syncthreads();

        const u32 sb = tiles + (u32)(c & 1) * (NT * TILE);
#pragma unroll
        for (int kk = 0; kk < 4; kk++) {
            u32 af[NSA][4][4];
#pragma unroll
            for (int s = 0; s < NSA; s++)
#pragma unroll
                for (int mf = 0; mf < 4; mf++) {
                    const u32 ad = sb + s * TILE +
                        SWZ((u32)((aRow + mf * 16) * 128 + kk * 32 + aKb));
                    ldsm4(af[s][mf][0], af[s][mf][1], af[s][mf][2], af[s][mf][3], ad);
                }
            u32 bfr[NSB][2][4];
#pragma unroll
            for (int s = 0; s < NSB; s++)
#pragma unroll
                for (int nfp = 0; nfp < 2; nfp++) {
                    const u32 ad = sb + (NSA + s) * TILE +
                        SWZ((u32)((bRow + nfp * 16) * 128 + kk * 32 + bKb));
                    ldsm4(bfr[s][nfp][0], bfr[s][nfp][1], bfr[s][nfp][2], bfr[s][nfp][3], ad);
                }
#pragma unroll
            for (int pp = 0; pp < NP; pp++) {
                const int ia = PI[pp], jb = PJ[pp];
#pragma unroll
                for (int mf = 0; mf < 4; mf++)
#pragma unroll
                    for (int nf = 0; nf < 4; nf++)
                        mma16816(acc[mf][nf], af[ia][mf],
                                 &bfr[jb][nf >> 1][(nf & 1) * 2]);
            }
        }
        __syncthreads();   // protect smem buffer reuse by next prefetch
    }

    // ---------------- epilogue from registers ----------------
    {
        float* Cg = (NEMIT == 0) ? ga.C + z * ga.sC : nullptr;
        bf16 *S0g = nullptr, *S1g = nullptr, *S2g = nullptr;
        if (NEMIT >= 2) { S0g = ga.S0 + z * ga.sC; S1g = ga.S1 + z * ga.sC; }
        if (NEMIT == 3) S2g = ga.S2 + z * ga.sC;

        const int erow = m0 + wy * 64 + (lane >> 2);
        const int ecol0 = n0 + wx * 32 + (lane & 3) * 2;

#pragma unroll
        for (int mf = 0; mf < 4; mf++) {
#pragma unroll
            for (int hh = 0; hh < 2; hh++) {
                const long row = erow + mf * 16 + hh * 8;
                const float br = (EPI & EPI_BIASR) ? ga.biasR[row] : 0.f;
                const long rbase = row * ga.ldc;
#pragma unroll
                for (int nf = 0; nf < 4; nf++) {
                    const int col = ecol0 + nf * 8;
                    float v0 = acc[mf][nf][hh * 2 + 0];
                    float v1 = acc[mf][nf][hh * 2 + 1];
                    if (EPI & EPI_BIAS) {
                        const float2 b = *reinterpret_cast<const float2*>(ga.bias + col);
                        v0 += b.x; v1 += b.y;
                    }
                    if (EPI & EPI_BIASR) { v0 += br; v1 += br; }
                    if (EPI & EPI_RES) {
                        const float2 r = *reinterpret_cast<const float2*>(ga.resid + rbase + col);
                        v0 += r.x; v1 += r.y;
                    }
                    if (EPI & EPI_RELU) { v0 = fmaxf(v0, 0.f); v1 = fmaxf(v1, 0.f); }
                    if (NEMIT == 0) {
                        *reinterpret_cast<float2*>(Cg + rbase + col) = make_float2(v0, v1);
                    } else {
                        bf16 a0, a1, b0, b1, c0, c1;
                        if (NEMIT == 3) { split3f(v0, a0, b0, c0); split3f(v1, a1, b1, c1); }
                        else            { split2f(v0, a0, b0);     split2f(v1, a1, b1); }
                        st_bf2(S0g + rbase + col, a0, a1);
                        st_bf2(S1g + rbase + col, b0, b1);
                        if (NEMIT == 3) st_bf2(S2g + rbase + col, c0, c1);
                    }
                }
            }
        }
    }
}

// ---------------- prep kernels ----------------
template<int NS>
__global__ void __launch_bounds__(256) splitAct(const float4* __restrict__ x,
                                                bf16* s0, bf16* s1, bf16* s2)
{
    const long i = (long)blockIdx.x * 256 + threadIdx.x;
    const float4 v = x[i];
    float f[4] = {v.x, v.y, v.z, v.w};
    bf16 a0[4], a1[4], a2[4];
#pragma unroll
    for (int j = 0; j < 4; j++) {
        if (NS == 3) split3f(f[j], a0[j], a1[j], a2[j]);
        else         split2f(f[j], a0[j], a1[j]);
    }
    st_bf2(s0 + 4 * i, a0[0], a0[1]); st_bf2(s0 + 4 * i + 2, a0[2], a0[3]);
    st_bf2(s1 + 4 * i, a1[0], a1[1]); st_bf2(s1 + 4 * i + 2, a1[2], a1[3]);
    if (NS == 3) { st_bf2(s2 + 4 * i, a2[0], a2[1]); st_bf2(s2 + 4 * i + 2, a2[2], a2[3]); }
}

// T[n][k] = split(W[k][n]); tiled transpose
template<int NS>
__global__ void __launch_bounds__(256) wsplitT(const float* __restrict__ W,
                                               bf16* t0, bf16* t1, bf16* t2)
{
    __shared__ float tile[32][33];
    const int bk = blockIdx.x * 32, bn = blockIdx.y * 32;
    const int tx = threadIdx.x & 31, ty = threadIdx.x >> 5;
#pragma unroll
    for (int i = ty; i < 32; i += 8)
        tile[i][tx] = W[(long)(bk + i) * DD + bn + tx];
    __syncthreads();
#pragma unroll
    for (int i = ty; i < 32; i += 8) {
        const float v = tile[tx][i];
        const long o = (long)(bn + i) * DD + bk + tx;
        bf16 a, b, c;
        if (NS == 3) { split3f(v, a, b, c); t2[o] = c; }
        else         split2f(v, a, b);
        t0[o] = a; t1[o] = b;
    }
}

__global__ void __launch_bounds__(256) softmax_split(const float* __restrict__ sc,
                                                     bf16* __restrict__ p0,
                                                     bf16* __restrict__ p1)
{
    __shared__ float red[8];
    __shared__ float bcast;
    const int t = threadIdx.x;
    const size_t base = (size_t)blockIdx.x * SS;
    const float* row = sc + base;
    float v[8];
#pragma unroll
    for (int i = 0; i < 8; i++) v[i] = row[t + i * 256];
    float m = v[0];
#pragma unroll
    for (int i = 1; i < 8; i++) m = fmaxf(m, v[i]);
#pragma unroll
    for (int o = 16; o; o >>= 1) m = fmaxf(m, __shfl_xor_sync(0xffffffffu, m, o));
    if ((t & 31) == 0) red[t >> 5] = m;
    __syncthreads();
    if (t == 0) {
        float mm = red[0];
#pragma unroll
        for (int i = 1; i < 8; i++) mm = fmaxf(mm, red[i]);
        bcast = mm;
    }
    __syncthreads();
    m = bcast;
    float s = 0.f;
#pragma unroll
    for (int i = 0; i < 8; i++) { v[i] = expf(v[i] - m); s += v[i]; }
#pragma unroll
    for (int o = 16; o; o >>= 1) s += __shfl_xor_sync(0xffffffffu, s, o);
    __syncthreads();
    if ((t & 31) == 0) red[t >> 5] = s;
    __syncthreads();
    if (t == 0) {
        float ss = 0.f;
#pragma unroll
        for (int i = 0; i < 8; i++) ss += red[i];
        bcast = 1.f / ss;
    }
    __syncthreads();
    const float inv = bcast;
#pragma unroll
    for (int i = 0; i < 8; i++) {
        bf16 a, b;
        split2f(v[i] * inv, a, b);
        p0[base + t + i * 256] = a;
        p1[base + t + i * 256] = b;
    }
}

__global__ void __launch_bounds__(256)
out_dot(const float* __restrict__ x, const float* __restrict__ W2,
        const float* __restrict__ b2, float* __restrict__ out)
{
    const int warp = threadIdx.x >> 5, lane = threadIdx.x & 31;
    const long row = (long)blockIdx.x * 8 + warp;
    const float* xr = x + row * DD;
    float s = 0.f;
#pragma unroll
    for (int i = 0; i < DD / 32; i++)
        s += xr[i * 32 + lane] * W2[i * 32 + lane];
#pragma unroll
    for (int o = 16; o; o >>= 1) s += __shfl_xor_sync(0xffffffffu, s, o);
    if (lane == 0) out[row] = s + b2[0];
}

// ---------------- host ----------------
extern "C" void kernel_launch(void* const* d_in, const int* in_sizes, int n_in,
                              void* d_out, int out_size)
{
    const float* visual = (const float*)d_in[0];
    const float* audio  = (const float*)d_in[1];
    const float* Wq = (const float*)d_in[2];  const float* bq = (const float*)d_in[3];
    const float* Wk = (const float*)d_in[4];  const float* bk = (const float*)d_in[5];
    const float* Wv = (const float*)d_in[6];  const float* bv = (const float*)d_in[7];
    const float* Wo = (const float*)d_in[8];  const float* bo = (const float*)d_in[9];
    const float* W1 = (const float*)d_in[10]; const float* b1 = (const float*)d_in[11];
    const float* W2 = (const float*)d_in[12]; const float* b2 = (const float*)d_in[13];
    float* out = (float*)d_out;

    char* pool;
    cudaGetSymbolAddress((void**)&pool, g_pool);
    auto act = [&](int i) { return (bf16*)(pool + (size_t)i * SZ_ACT); };
    bf16 *vis0 = act(0), *vis1 = act(1), *vis2 = act(2);
    bf16 *aud0 = act(3), *aud1 = act(4), *aud2 = act(5);
    bf16 *q0 = act(6),  *q1 = act(7),  *q2 = act(8);
    bf16 *k0 = act(9),  *k1 = act(10), *k2 = act(11);
    bf16 *vt0 = act(12), *vt1 = act(13);
    bf16 *at0 = act(14), *at1 = act(15);
    bf16 *h0 = act(16),  *h1 = act(17);
    bf16 *p0 = (bf16*)(pool + O_P0), *p1 = (bf16*)(pool + O_P1);
    auto wt = [&](int i) { return (bf16*)(pool + O_WT + (size_t)i * SZ_W); };
    float* sc = (float*)(pool + O_SC);
    float* gx = (float*)(pool + O_X);

    const int SM33 = 1024 + 2 * 6 * 16384;   // 197,632
    const int SM22 = 1024 + 2 * 4 * 16384;   // 132,096
    cudaFuncSetAttribute((const void*)mma_gemm<3,3,6,EPI_BIAS,3>,  cudaFuncAttributeMaxDynamicSharedMemorySize, SM33);
    cudaFuncSetAttribute((const void*)mma_gemm<3,3,6,0,0>,         cudaFuncAttributeMaxDynamicSharedMemorySize, SM33);
    cudaFuncSetAttribute((const void*)mma_gemm<2,2,3,EPI_BIASR,2>, cudaFuncAttributeMaxDynamicSharedMemorySize, SM22);
    cudaFuncSetAttribute((const void*)mma_gemm<2,2,3,0,2>,         cudaFuncAttributeMaxDynamicSharedMemorySize, SM22);
    cudaFuncSetAttribute((const void*)mma_gemm<2,2,3,EPI_BIAS|EPI_RES,2>,  cudaFuncAttributeMaxDynamicSharedMemorySize, SM22);
    cudaFuncSetAttribute((const void*)mma_gemm<2,2,3,EPI_BIAS|EPI_RELU,0>, cudaFuncAttributeMaxDynamicSharedMemorySize, SM22);

    const int nb4 = (MTOT * DD) / 4 / 256;
    splitAct<3><<<nb4, 256>>>((const float4*)visual, vis0, vis1, vis2);
    splitAct<3><<<nb4, 256>>>((const float4*)audio,  aud0, aud1, aud2);
    const dim3 gw(DD / 32, DD / 32);
    wsplitT<3><<<gw, 256>>>(Wq, wt(0), wt(1), wt(2));
    wsplitT<3><<<gw, 256>>>(Wk, wt(3), wt(4), wt(5));
    wsplitT<2><<<gw, 256>>>(Wv, wt(6), wt(7), nullptr);
    wsplitT<2><<<gw, 256>>>(Wo, wt(8), wt(9), nullptr);
    wsplitT<2><<<gw, 256>>>(W1, wt(10), wt(11), nullptr);

    GArgs a;
    // Q = visual @ Wq + bq -> q splits x3
    a = {vis0, vis1, vis2, wt(0), wt(1), wt(2), nullptr, q0, q1, q2,
         bq, nullptr, nullptr, DD, DD, DD, DD, 0, 0, 0};
    mma_gemm<3,3,6,EPI_BIAS,3><<<dim3(8, 128, 1), 256, SM33>>>(a);
    // K = audio @ Wk + bk -> k splits x3
    a = {aud0, aud1, aud2, wt(3), wt(4), wt(5), nullptr, k0, k1, k2,
         bk, nullptr, nullptr, DD, DD, DD, DD, 0, 0, 0};
    mma_gemm<3,3,6,EPI_BIAS,3><<<dim3(8, 128, 1), 256, SM33>>>(a);
    // V^T[e, t] = WvT @ audio^T + bv(row e) -> vt splits x2  [DD x MTOT], ldc=MTOT
    a = {wt(6), wt(7), nullptr, aud0, aud1, nullptr, nullptr, vt0, vt1, nullptr,
         nullptr, bv, nullptr, DD, DD, DD, MTOT, 0, 0, 0};
    mma_gemm<2,2,3,EPI_BIASR,2><<<dim3(128, 8, 1), 256, SM22>>>(a);
    // scores[b] = Q[b] @ K[b]^T -> fp32
    a = {q0, q1, q2, k0, k1, k2, sc, nullptr, nullptr, nullptr,
         nullptr, nullptr, nullptr, DD, DD, DD, SS,
         (long)SS * DD, (long)SS * DD, (long)SS * SS};
    mma_gemm<3,3,6,0,0><<<dim3(16, 16, BB), 256, SM33>>>(a);
    // softmax -> p splits x2
    softmax_split<<<MTOT, 256>>>(sc, p0, p1);
    // att[b] = P[b] @ V[b] -> at splits x2 (B = V^T slice: ldb=MTOT, sB=SS)
    a = {p0, p1, nullptr, vt0, vt1, nullptr, nullptr, at0, at1, nullptr,
         nullptr, nullptr, nullptr, SS, SS, MTOT, DD,
         (long)SS * SS, (long)SS, (long)SS * DD};
    mma_gemm<2,2,3,0,2><<<dim3(8, 16, BB), 256, SM22>>>(a);
    // h = att @ Wo + bo + visual -> h splits x2
    a = {at0, at1, nullptr, wt(8), wt(9), nullptr, nullptr, h0, h1, nullptr,
         bo, nullptr, visual, DD, DD, DD, DD, 0, 0, 0};
    mma_gemm<2,2,3,EPI_BIAS|EPI_RES,2><<<dim3(8, 128, 1), 256, SM22>>>(a);
    // x = relu(h @ W1 + b1) -> fp32
    a = {h0, h1, nullptr, wt(10), wt(11), nullptr, gx, nullptr, nullptr, nullptr,
         b1, nullptr, nullptr, DD, DD, DD, DD, 0, 0, 0};
    mma_gemm<2,2,3,EPI_BIAS|EPI_RELU,0><<<dim3(8, 128, 1), 256, SM22>>>(a);
    // out = x @ W2 + b2
    out_dot<<<MTOT / 8, 256>>>(gx, W2, b2, out);
}

// round 7
// speedup vs baseline: 2.9485x; 1.3548x over previous
#include <cuda_runtime.h>
#include <cuda_bf16.h>
#include <cstdint>

typedef __nv_bfloat16 bf16;
typedef unsigned int u32;
typedef unsigned long long u64;

#define BB 8
#define SS 2048
#define DD 1024
#define MTOT (BB*SS)

// ---------------- scratch pool ----------------
constexpr size_t SZ_ACT = (size_t)MTOT * DD * 2;
constexpr size_t SZ_P   = (size_t)BB * SS * SS * 2;
constexpr size_t SZ_W   = (size_t)DD * DD * 2;
constexpr size_t SZ_SC  = (size_t)BB * SS * SS * 4;
constexpr size_t SZ_X   = (size_t)MTOT * DD * 4;
constexpr int N_ACT = 14;
constexpr size_t O_P0 = (size_t)N_ACT * SZ_ACT;
constexpr size_t O_P1 = O_P0 + SZ_P;
constexpr size_t O_WT = O_P1 + SZ_P;
constexpr size_t O_SC = O_WT + 10 * SZ_W;
constexpr size_t O_X  = O_SC + SZ_SC;
__device__ __align__(256) char g_pool[O_X + SZ_X];

// ---------------- helpers ----------------
__device__ __forceinline__ u32 smem_to_u32(const void* p) {
    u32 a;
    asm("{ .reg .u64 t; cvta.to.shared.u64 t, %1; cvt.u32.u64 %0, t; }" : "=r"(a) : "l"(p));
    return a;
}
#define SWZ(off) ((off) ^ (((off) >> 3) & 0x70))

__device__ __forceinline__ void cp16(u32 s, const void* g) {
    asm volatile("cp.async.cg.shared.global [%0], [%1], 16;" :: "r"(s), "l"(g));
}
__device__ __forceinline__ void ldsm4(u32& r0, u32& r1, u32& r2, u32& r3, u32 a) {
    asm volatile("ldmatrix.sync.aligned.m8n8.x4.shared.b16 {%0,%1,%2,%3}, [%4];"
                 : "=r"(r0), "=r"(r1), "=r"(r2), "=r"(r3) : "r"(a));
}
__device__ __forceinline__ void mma16816(float* c, const u32* a, const u32* b) {
    asm("mma.sync.aligned.m16n8k16.row.col.f32.bf16.bf16.f32 "
        "{%0,%1,%2,%3},{%4,%5,%6,%7},{%8,%9},{%0,%1,%2,%3};"
        : "+f"(c[0]), "+f"(c[1]), "+f"(c[2]), "+f"(c[3])
        : "r"(a[0]), "r"(a[1]), "r"(a[2]), "r"(a[3]), "r"(b[0]), "r"(b[1]));
}

__device__ __forceinline__ void split2f(float v, bf16& a, bf16& b) {
    a = __float2bfloat16(v);
    b = __float2bfloat16(v - __bfloat162float(a));
}
__device__ __forceinline__ void st_bf2(bf16* p, bf16 a, bf16 b) {
    __nv_bfloat162 t; t.x = a; t.y = b;
    *reinterpret_cast<__nv_bfloat162*>(p) = t;
}

enum { EPI_BIAS = 1, EPI_RES = 2, EPI_RELU = 4, EPI_BIASR = 8 };

struct GArgs {
    const bf16 *A0, *A1, *B0, *B1;
    float* C;
    bf16 *S0, *S1;
    const float *bias, *biasR, *resid;
    int K, lda, ldb, ldc;
    long sA, sB, sC;
};

// C[M,N] = (A0+A1)[M,K] @ (B0+B1)[N,K]^T via 3 split products, fp32 accum.
// Block 128x128, K-chunks of 64 bf16 (SW128 rows), 3-stage cp.async pipeline,
// 8 warps 2(M)x4(N), warp tile 64x32, mma.sync m16n8k16. One barrier per chunk.
template<int EPI, int NEMIT>
__global__ void __launch_bounds__(256, 1) mma_gemm(const GArgs ga)
{
    extern __shared__ char dynsmem[];
    constexpr int NT = 4;                 // A0,A1,B0,B1 tiles
    constexpr int TILE = 16384;
    constexpr int NSTAGE = 3;
    constexpr int PI[3] = {0, 0, 1};
    constexpr int PJ[3] = {0, 1, 0};

    const int tid = threadIdx.x, wid = tid >> 5, lane = tid & 31;
    const u32 tiles = (smem_to_u32(dynsmem) + 1023u) & ~1023u;
    const long z = blockIdx.z;
    const int m0 = blockIdx.y * 128, n0 = blockIdx.x * 128;

    const bf16* src[NT];
    src[0] = ga.A0 + z * ga.sA + (long)m0 * ga.lda;
    src[1] = ga.A1 + z * ga.sA + (long)m0 * ga.lda;
    src[2] = ga.B0 + z * ga.sB + (long)n0 * ga.ldb;
    src[3] = ga.B1 + z * ga.sB + (long)n0 * ga.ldb;

    const int wy = wid & 1, wx = wid >> 1;   // warp tile: rows wy*64, cols wx*32

    float acc[4][4][4];
#pragma unroll
    for (int i = 0; i < 4; i++)
#pragma unroll
        for (int j = 0; j < 4; j++)
#pragma unroll
            for (int r = 0; r < 4; r++) acc[i][j][r] = 0.f;

    const int aRow = wy * 64 + (lane & 15);
    const int aKb  = (lane >> 4) * 16;
    const int bRow = wx * 32 + (lane & 7) + ((lane >> 4) & 1) * 8;
    const int bKb  = ((lane >> 3) & 1) * 16;

    auto load_chunk = [&](int k0, int buf) {
        const u32 sb = tiles + (u32)buf * (NT * TILE);
#pragma unroll
        for (int t = 0; t < NT; t++) {
            const int ld = (t < 2) ? ga.lda : ga.ldb;
#pragma unroll
            for (int u = 0; u < 4; u++) {
                const int i = u * 256 + tid;
                const int r = i >> 3, c16 = i & 7;
                cp16(sb + t * TILE + SWZ((r << 7) + (c16 << 4)),
                     src[t] + (long)r * ld + k0 + c16 * 8);
            }
        }
        asm volatile("cp.async.commit_group;" ::: "memory");
    };

    const int NC = ga.K >> 6;
    load_chunk(0, 0);
    if (NC > 1) load_chunk(64, 1);

    int buf = 0, nbuf = 2;
    for (int c = 0; c < NC; ++c) {
        if (c + 1 < NC) {
            asm volatile("cp.async.wait_group 1;" ::: "memory");
        } else {
            asm volatile("cp.async.wait_group 0;" ::: "memory");
        }
        __syncthreads();
        if (c + 2 < NC) {
            load_chunk((c + 2) << 6, nbuf);
            if (++nbuf == NSTAGE) nbuf = 0;
        }

        const u32 sb = tiles + (u32)buf * (NT * TILE);
        if (++buf == NSTAGE) buf = 0;
#pragma unroll
        for (int kk = 0; kk < 4; kk++) {
            u32 af[2][4][4];
#pragma unroll
            for (int s = 0; s < 2; s++)
#pragma unroll
                for (int mf = 0; mf < 4; mf++) {
                    const u32 ad = sb + s * TILE +
                        SWZ((u32)((aRow + mf * 16) * 128 + kk * 32 + aKb));
                    ldsm4(af[s][mf][0], af[s][mf][1], af[s][mf][2], af[s][mf][3], ad);
                }
            u32 bfr[2][2][4];
#pragma unroll
            for (int s = 0; s < 2; s++)
#pragma unroll
                for (int nfp = 0; nfp < 2; nfp++) {
                    const u32 ad = sb + (2 + s) * TILE +
                        SWZ((u32)((bRow + nfp * 16) * 128 + kk * 32 + bKb));
                    ldsm4(bfr[s][nfp][0], bfr[s][nfp][1], bfr[s][nfp][2], bfr[s][nfp][3], ad);
                }
#pragma unroll
            for (int pp = 0; pp < 3; pp++) {
                const int ia = PI[pp], jb = PJ[pp];
#pragma unroll
                for (int mf = 0; mf < 4; mf++)
#pragma unroll
                    for (int nf = 0; nf < 4; nf++)
                        mma16816(acc[mf][nf], af[ia][mf],
                                 &bfr[jb][nf >> 1][(nf & 1) * 2]);
            }
        }
    }

    // ---------------- epilogue from registers ----------------
    {
        float* Cg = (NEMIT == 0) ? ga.C + z * ga.sC : nullptr;
        bf16 *S0g = nullptr, *S1g = nullptr;
        if (NEMIT == 2) { S0g = ga.S0 + z * ga.sC; S1g = ga.S1 + z * ga.sC; }

        const int erow = m0 + wy * 64 + (lane >> 2);
        const int ecol0 = n0 + wx * 32 + (lane & 3) * 2;

#pragma unroll
        for (int mf = 0; mf < 4; mf++) {
#pragma unroll
            for (int hh = 0; hh < 2; hh++) {
                const long row = erow + mf * 16 + hh * 8;
                const float br = (EPI & EPI_BIASR) ? ga.biasR[row] : 0.f;
                const long rbase = row * ga.ldc;
#pragma unroll
                for (int nf = 0; nf < 4; nf++) {
                    const int col = ecol0 + nf * 8;
                    float v0 = acc[mf][nf][hh * 2 + 0];
                    float v1 = acc[mf][nf][hh * 2 + 1];
                    if (EPI & EPI_BIAS) {
                        const float2 b = *reinterpret_cast<const float2*>(ga.bias + col);
                        v0 += b.x; v1 += b.y;
                    }
                    if (EPI & EPI_BIASR) { v0 += br; v1 += br; }
                    if (EPI & EPI_RES) {
                        const float2 r = *reinterpret_cast<const float2*>(ga.resid + rbase + col);
                        v0 += r.x; v1 += r.y;
                    }
                    if (EPI & EPI_RELU) { v0 = fmaxf(v0, 0.f); v1 = fmaxf(v1, 0.f); }
                    if (NEMIT == 0) {
                        *reinterpret_cast<float2*>(Cg + rbase + col) = make_float2(v0, v1);
                    } else {
                        bf16 a0, a1, b0, b1;
                        split2f(v0, a0, b0);
                        split2f(v1, a1, b1);
                        st_bf2(S0g + rbase + col, a0, a1);
                        st_bf2(S1g + rbase + col, b0, b1);
                    }
                }
            }
        }
    }
}

// ---------------- prep kernels ----------------
__global__ void __launch_bounds__(256) splitAct2(const float4* __restrict__ x,
                                                 bf16* s0, bf16* s1)
{
    const long i = (long)blockIdx.x * 256 + threadIdx.x;
    const float4 v = x[i];
    float f[4] = {v.x, v.y, v.z, v.w};
    bf16 a0[4], a1[4];
#pragma unroll
    for (int j = 0; j < 4; j++) split2f(f[j], a0[j], a1[j]);
    st_bf2(s0 + 4 * i, a0[0], a0[1]); st_bf2(s0 + 4 * i + 2, a0[2], a0[3]);
    st_bf2(s1 + 4 * i, a1[0], a1[1]); st_bf2(s1 + 4 * i + 2, a1[2], a1[3]);
}

// T[n][k] = split(W[k][n]); tiled transpose
__global__ void __launch_bounds__(256) wsplitT2(const float* __restrict__ W,
                                                bf16* t0, bf16* t1)
{
    __shared__ float tile[32][33];
    const int bk = blockIdx.x * 32, bn = blockIdx.y * 32;
    const int tx = threadIdx.x & 31, ty = threadIdx.x >> 5;
#pragma unroll
    for (int i = ty; i < 32; i += 8)
        tile[i][tx] = W[(long)(bk + i) * DD + bn + tx];
    __syncthreads();
#pragma unroll
    for (int i = ty; i < 32; i += 8) {
        const float v = tile[tx][i];
        const long o = (long)(bn + i) * DD + bk + tx;
        bf16 a, b;
        split2f(v, a, b);
        t0[o] = a; t1[o] = b;
    }
}

__global__ void __launch_bounds__(256) softmax_split(const float* __restrict__ sc,
                                                     bf16* __restrict__ p0,
                                                     bf16* __restrict__ p1)
{
    __shared__ float red[8];
    __shared__ float bcast;
    const int t = threadIdx.x;
    const size_t base = (size_t)blockIdx.x * SS;
    const float* row = sc + base;
    float v[8];
#pragma unroll
    for (int i = 0; i < 8; i++) v[i] = row[t + i * 256];
    float m = v[0];
#pragma unroll
    for (int i = 1; i < 8; i++) m = fmaxf(m, v[i]);
#pragma unroll
    for (int o = 16; o; o >>= 1) m = fmaxf(m, __shfl_xor_sync(0xffffffffu, m, o));
    if ((t & 31) == 0) red[t >> 5] = m;
    __syncthreads();
    if (t == 0) {
        float mm = red[0];
#pragma unroll
        for (int i = 1; i < 8; i++) mm = fmaxf(mm, red[i]);
        bcast = mm;
    }
    __syncthreads();
    m = bcast;
    float s = 0.f;
#pragma unroll
    for (int i = 0; i < 8; i++) { v[i] = expf(v[i] - m); s += v[i]; }
#pragma unroll
    for (int o = 16; o; o >>= 1) s += __shfl_xor_sync(0xffffffffu, s, o);
    __syncthreads();
    if ((t & 31) == 0) red[t >> 5] = s;
    __syncthreads();
    if (t == 0) {
        float ss = 0.f;
#pragma unroll
        for (int i = 0; i < 8; i++) ss += red[i];
        bcast = 1.f / ss;
    }
    __syncthreads();
    const float inv = bcast;
#pragma unroll
    for (int i = 0; i < 8; i++) {
        bf16 a, b;
        split2f(v[i] * inv, a, b);
        p0[base + t + i * 256] = a;
        p1[base + t + i * 256] = b;
    }
}

__global__ void __launch_bounds__(256)
out_dot(const float* __restrict__ x, const float* __restrict__ W2,
        const float* __restrict__ b2, float* __restrict__ out)
{
    const int warp = threadIdx.x >> 5, lane = threadIdx.x & 31;
    const long row = (long)blockIdx.x * 8 + warp;
    const float* xr = x + row * DD;
    float s = 0.f;
#pragma unroll
    for (int i = 0; i < DD / 32; i++)
        s += xr[i * 32 + lane] * W2[i * 32 + lane];
#pragma unroll
    for (int o = 16; o; o >>= 1) s += __shfl_xor_sync(0xffffffffu, s, o);
    if (lane == 0) out[row] = s + b2[0];
}

// ---------------- host ----------------
extern "C" void kernel_launch(void* const* d_in, const int* in_sizes, int n_in,
                              void* d_out, int out_size)
{
    const float* visual = (const float*)d_in[0];
    const float* audio  = (const float*)d_in[1];
    const float* Wq = (const float*)d_in[2];  const float* bq = (const float*)d_in[3];
    const float* Wk = (const float*)d_in[4];  const float* bk = (const float*)d_in[5];
    const float* Wv = (const float*)d_in[6];  const float* bv = (const float*)d_in[7];
    const float* Wo = (const float*)d_in[8];  const float* bo = (const float*)d_in[9];
    const float* W1 = (const float*)d_in[10]; const float* b1 = (const float*)d_in[11];
    const float* W2 = (const float*)d_in[12]; const float* b2 = (const float*)d_in[13];
    float* out = (float*)d_out;

    char* pool;
    cudaGetSymbolAddress((void**)&pool, g_pool);
    auto act = [&](int i) { return (bf16*)(pool + (size_t)i * SZ_ACT); };
    bf16 *vis0 = act(0), *vis1 = act(1);
    bf16 *aud0 = act(2), *aud1 = act(3);
    bf16 *q0 = act(4),  *q1 = act(5);
    bf16 *k0 = act(6),  *k1 = act(7);
    bf16 *vt0 = act(8), *vt1 = act(9);
    bf16 *at0 = act(10), *at1 = act(11);
    bf16 *h0 = act(12),  *h1 = act(13);
    bf16 *p0 = (bf16*)(pool + O_P0), *p1 = (bf16*)(pool + O_P1);
    auto wt = [&](int i) { return (bf16*)(pool + O_WT + (size_t)i * SZ_W); };
    float* sc = (float*)(pool + O_SC);
    float* gx = (float*)(pool + O_X);

    const int SMEM = 1024 + 3 * 4 * 16384;   // 197,632
    cudaFuncSetAttribute((const void*)mma_gemm<EPI_BIAS,2>,  cudaFuncAttributeMaxDynamicSharedMemorySize, SMEM);
    cudaFuncSetAttribute((const void*)mma_gemm<EPI_BIASR,2>, cudaFuncAttributeMaxDynamicSharedMemorySize, SMEM);
    cudaFuncSetAttribute((const void*)mma_gemm<0,0>,         cudaFuncAttributeMaxDynamicSharedMemorySize, SMEM);
    cudaFuncSetAttribute((const void*)mma_gemm<0,2>,         cudaFuncAttributeMaxDynamicSharedMemorySize, SMEM);
    cudaFuncSetAttribute((const void*)mma_gemm<EPI_BIAS|EPI_RES,2>,  cudaFuncAttributeMaxDynamicSharedMemorySize, SMEM);
    cudaFuncSetAttribute((const void*)mma_gemm<EPI_BIAS|EPI_RELU,0>, cudaFuncAttributeMaxDynamicSharedMemorySize, SMEM);

    const int nb4 = (MTOT * DD) / 4 / 256;
    splitAct2<<<nb4, 256>>>((const float4*)visual, vis0, vis1);
    splitAct2<<<nb4, 256>>>((const float4*)audio,  aud0, aud1);
    const dim3 gw(DD / 32, DD / 32);
    wsplitT2<<<gw, 256>>>(Wq, wt(0), wt(1));
    wsplitT2<<<gw, 256>>>(Wk, wt(2), wt(3));
    wsplitT2<<<gw, 256>>>(Wv, wt(4), wt(5));
    wsplitT2<<<gw, 256>>>(Wo, wt(6), wt(7));
    wsplitT2<<<gw, 256>>>(W1, wt(8), wt(9));

    GArgs a;
    // Q = visual @ Wq + bq -> q splits
    a = {vis0, vis1, wt(0), wt(1), nullptr, q0, q1,
         bq, nullptr, nullptr, DD, DD, DD, DD, 0, 0, 0};
    mma_gemm<EPI_BIAS,2><<<dim3(8, 128, 1), 256, SMEM>>>(a);
    // K = audio @ Wk + bk -> k splits
    a = {aud0, aud1, wt(2), wt(3), nullptr, k0, k1,
         bk, nullptr, nullptr, DD, DD, DD, DD, 0, 0, 0};
    mma_gemm<EPI_BIAS,2><<<dim3(8, 128, 1), 256, SMEM>>>(a);
    // V^T[e, t] = WvT @ audio^T + bv(row e) -> vt splits  [DD x MTOT], ldc=MTOT
    a = {wt(4), wt(5), aud0, aud1, nullptr, vt0, vt1,
         nullptr, bv, nullptr, DD, DD, DD, MTOT, 0, 0, 0};
    mma_gemm<EPI_BIASR,2><<<dim3(128, 8, 1), 256, SMEM>>>(a);
    // scores[b] = Q[b] @ K[b]^T -> fp32
    a = {q0, q1, k0, k1, sc, nullptr, nullptr,
         nullptr, nullptr, nullptr, DD, DD, DD, SS,
         (long)SS * DD, (long)SS * DD, (long)SS * SS};
    mma_gemm<0,0><<<dim3(16, 16, BB), 256, SMEM>>>(a);
    // softmax -> p splits
    softmax_split<<<MTOT, 256>>>(sc, p0, p1);
    // att[b] = P[b] @ V[b] -> at splits (B = V^T slice: ldb=MTOT, sB=SS)
    a = {p0, p1, vt0, vt1, nullptr, at0, at1,
         nullptr, nullptr, nullptr, SS, SS, MTOT, DD,
         (long)SS * SS, (long)SS, (long)SS * DD};
    mma_gemm<0,2><<<dim3(8, 16, BB), 256, SMEM>>>(a);
    // h = att @ Wo + bo + visual -> h splits
    a = {at0, at1, wt(6), wt(7), nullptr, h0, h1,
         bo, nullptr, visual, DD, DD, DD, DD, 0, 0, 0};
    mma_gemm<EPI_BIAS|EPI_RES,2><<<dim3(8, 128, 1), 256, SMEM>>>(a);
    // x = relu(h @ W1 + b1) -> fp32
    a = {h0, h1, wt(8), wt(9), gx, nullptr, nullptr,
         b1, nullptr, nullptr, DD, DD, DD, DD, 0, 0, 0};
    mma_gemm<EPI_BIAS|EPI_RELU,0><<<dim3(8, 128, 1), 256, SMEM>>>(a);
    // out = x @ W2 + b2
    out_dot<<<MTOT / 8, 256>>>(gx, W2, b2, out);
}